// round 9
// baseline (speedup 1.0000x reference)
#include <cuda_runtime.h>
#include <cuda_bf16.h>

#define NIDS    33                       // ids 0..32 (0 = background)
#define NBINS   1089                     // 33*33
#define THREADS 512                      // 16 warps per CTA
#define NREP    16                       // replicated global histograms
#define GRP_BYTES (NBINS * 32)           // one slot-group: u8[bin][lane]
#define SMEM_DYN  (2 * GRP_BYTES)        // 69,696 B  (two groups: warps split by w&1)

// Scratch (zero at load; finalize block resets after every call)
__device__ int          g_rep[NREP][NBINS];
__device__ unsigned int g_ticket;

__global__ void __launch_bounds__(THREADS, 2)
fused_iou_kernel(const float4* __restrict__ p4, const float4* __restrict__ t4,
                 int n4,
                 const float* __restrict__ pf, const float* __restrict__ tf,
                 int n, float* __restrict__ out, int nblocks)
{
    extern __shared__ unsigned char cnt[];   // [2][NBINS][32]: bank = lane, conflict-free
    __shared__ float psum[NIDS], tsum[NIDS], part[NIDS];
    __shared__ int   s_last;

    int tid  = threadIdx.x;
    int lane = tid & 31;
    int grp  = ((tid >> 5) & 1) * GRP_BYTES; // warp-half -> slot group (8 warps share one)

    // ---- zero byte counters ----
    {
        uint4* z4 = (uint4*)cnt;
        #pragma unroll 3
        for (int i = tid; i < SMEM_DYN / 16; i += THREADS)
            z4[i] = make_uint4(0u, 0u, 0u, 0u);
    }
    __syncthreads();

    int gid    = blockIdx.x * THREADS + tid;
    int stride = gridDim.x * THREADS;

    // ---- main loop: warp-granular non-atomic byte RMW (4 LDS then 4 STS) ----
    int i = gid;
    for (; i + stride < n4; i += 2 * stride) {
        float4 P0 = p4[i];
        float4 T0 = t4[i];
        float4 P1 = p4[i + stride];
        float4 T1 = t4[i + stride];

        int i0 = ((int)fmaf(P0.x, 33.0f, T0.x)) * 32 + lane + grp;  // bin = 33*p + t
        int i1 = ((int)fmaf(P0.y, 33.0f, T0.y)) * 32 + lane + grp;
        int i2 = ((int)fmaf(P0.z, 33.0f, T0.z)) * 32 + lane + grp;
        int i3 = ((int)fmaf(P0.w, 33.0f, T0.w)) * 32 + lane + grp;
        unsigned char a0 = cnt[i0], a1 = cnt[i1], a2 = cnt[i2], a3 = cnt[i3];
        cnt[i0] = a0 + 1; cnt[i1] = a1 + 1; cnt[i2] = a2 + 1; cnt[i3] = a3 + 1;

        int j0 = ((int)fmaf(P1.x, 33.0f, T1.x)) * 32 + lane + grp;
        int j1 = ((int)fmaf(P1.y, 33.0f, T1.y)) * 32 + lane + grp;
        int j2 = ((int)fmaf(P1.z, 33.0f, T1.z)) * 32 + lane + grp;
        int j3 = ((int)fmaf(P1.w, 33.0f, T1.w)) * 32 + lane + grp;
        unsigned char b0 = cnt[j0], b1 = cnt[j1], b2 = cnt[j2], b3 = cnt[j3];
        cnt[j0] = b0 + 1; cnt[j1] = b1 + 1; cnt[j2] = b2 + 1; cnt[j3] = b3 + 1;
    }
    if (i < n4) {
        float4 P = p4[i], T = t4[i];
        int i0 = ((int)fmaf(P.x, 33.0f, T.x)) * 32 + lane + grp;
        int i1 = ((int)fmaf(P.y, 33.0f, T.y)) * 32 + lane + grp;
        int i2 = ((int)fmaf(P.z, 33.0f, T.z)) * 32 + lane + grp;
        int i3 = ((int)fmaf(P.w, 33.0f, T.w)) * 32 + lane + grp;
        unsigned char a0 = cnt[i0], a1 = cnt[i1], a2 = cnt[i2], a3 = cnt[i3];
        cnt[i0] = a0 + 1; cnt[i1] = a1 + 1; cnt[i2] = a2 + 1; cnt[i3] = a3 + 1;
    }
    __syncthreads();

    // ---- flush: per bin, dp4a-sum 64 bytes (2 groups x 8 words) ----
    int rep = blockIdx.x & (NREP - 1);
    const unsigned int* cw = (const unsigned int*)cnt;
    for (int b = tid; b < NBINS; b += THREADS) {
        unsigned int s = 0;
        #pragma unroll
        for (int k = 0; k < 8; k++) {
            s += __dp4a(cw[b * 8 + k],             0x01010101u, 0u);
            s += __dp4a(cw[NBINS * 8 + b * 8 + k], 0x01010101u, 0u);
        }
        if (s) atomicAdd(&g_rep[rep][b], (int)s);
    }
    __threadfence();

    // ---- ticket: last block finalizes ----
    if (tid == 0) {
        unsigned int t = atomicAdd(&g_ticket, 1u);
        s_last = (t == (unsigned int)(nblocks - 1));
    }
    __syncthreads();
    if (!s_last) return;

    int* h = (int*)cnt;   // reuse dynamic smem for the final histogram

    for (int b = tid; b < NBINS; b += THREADS) {
        int s = 0;
        #pragma unroll
        for (int r = 0; r < NREP; r++) { s += g_rep[r][b]; g_rep[r][b] = 0; }
        h[b] = s;
    }
    __syncthreads();
    if (tid == 0) {
        for (int k = n4 * 4; k < n; k++)               // scalar tail (n % 4)
            h[(int)fmaf(pf[k], 33.0f, tf[k])]++;
        g_ticket = 0u;
    }
    __syncthreads();

    if (tid < NIDS) {
        int s = 0;
        #pragma unroll
        for (int m = 0; m < NIDS; m++) s += h[tid * NIDS + m];
        psum[tid] = (float)s;
    } else if (tid >= 64 && tid < 64 + NIDS) {
        int m = tid - 64, s = 0;
        #pragma unroll
        for (int nn = 0; nn < NIDS; nn++) s += h[nn * NIDS + m];
        tsum[m] = (float)s;
    }
    __syncthreads();

    if (tid >= 1 && tid <= 32) {
        float pn = psum[tid];
        float max_iou = 0.0f;
        #pragma unroll
        for (int m = 1; m < NIDS; m++) {
            float inter = (float)h[tid * NIDS + m];
            float uni   = pn + tsum[m] - inter;
            float iou   = (uni > 0.0f) ? (inter / uni) : 0.0f;
            max_iou = fmaxf(max_iou, iou);
        }
        part[tid] = 1.0f - max_iou;
    }
    __syncthreads();

    if (tid == 0) {
        float loss = 0.0f;
        for (int nn = 1; nn <= 32; nn++) loss += part[nn];
        double sp = 0.0, st = 0.0;                      // dummy term
        for (int id = 1; id < NIDS; id++) {
            sp += (double)id * (double)psum[id];
            st += (double)id * (double)tsum[id];
        }
        loss += (float)((sp + st) * 1e-12);
        out[0] = loss;
    }
}

extern "C" void kernel_launch(void* const* d_in, const int* in_sizes, int n_in,
                              void* d_out, int out_size) {
    const float* pred  = (const float*)d_in[0];
    const float* truem = (const float*)d_in[1];
    float* out = (float*)d_out;
    int n  = in_sizes[0];
    int n4 = n / 4;

    cudaFuncSetAttribute(fused_iou_kernel,
                         cudaFuncAttributeMaxDynamicSharedMemorySize, SMEM_DYN);

    int sm_count = 148;
    cudaDeviceGetAttribute(&sm_count, cudaDevAttrMultiProcessorCount, 0);
    int blocks = sm_count * 2;   // 2 CTAs/SM x 69.7 KB smem, 32 warps/SM

    fused_iou_kernel<<<blocks, THREADS, SMEM_DYN>>>(
        (const float4*)pred, (const float4*)truem, n4,
        pred, truem, n, out, blocks);
}

// round 10
// speedup vs baseline: 1.1913x; 1.1913x over previous
#include <cuda_runtime.h>
#include <cuda_bf16.h>

#define NIDS    33                     // ids 0..32 (0 = background)
#define NBINS   1089                   // 33*33
#define THREADS 384                    // 12 warps per CTA
#define NREP    16                     // replicated global histograms
#define SMEM_DYN (NBINS * 32)          // u8[bin][lane] = 34,848 B; bank = lane

// Scratch (zero at load; finalize block resets after every call)
__device__ int          g_rep[NREP][NBINS];
__device__ unsigned int g_ticket;

__global__ void __launch_bounds__(THREADS, 4)
fused_iou_kernel(const float4* __restrict__ p4, const float4* __restrict__ t4,
                 int n4,
                 const float* __restrict__ pf, const float* __restrict__ tf,
                 int n, float* __restrict__ out, int nblocks)
{
    extern __shared__ unsigned char cnt[];   // [NBINS][32]: conflict-free byte slots
    __shared__ float psum[NIDS], tsum[NIDS], part[NIDS];
    __shared__ int   s_last;

    int tid  = threadIdx.x;
    int lane = tid & 31;

    // ---- zero byte counters ----
    {
        uint4* z4 = (uint4*)cnt;
        #pragma unroll 6
        for (int i = tid; i < SMEM_DYN / 16; i += THREADS)
            z4[i] = make_uint4(0u, 0u, 0u, 0u);
    }
    __syncthreads();

    int gid    = blockIdx.x * THREADS + tid;
    int stride = gridDim.x * THREADS;

    // ---- main loop: 8 pixels/trip; 4 LDG -> 8 independent LDS -> 8 STS ----
    int i = gid;
    for (; i + stride < n4; i += 2 * stride) {
        float4 P0 = p4[i];
        float4 T0 = t4[i];
        float4 P1 = p4[i + stride];
        float4 T1 = t4[i + stride];

        int i0 = (((int)fmaf(P0.x, 33.0f, T0.x)) << 5) + lane;   // bin = 33*p + t
        int i1 = (((int)fmaf(P0.y, 33.0f, T0.y)) << 5) + lane;
        int i2 = (((int)fmaf(P0.z, 33.0f, T0.z)) << 5) + lane;
        int i3 = (((int)fmaf(P0.w, 33.0f, T0.w)) << 5) + lane;
        int i4 = (((int)fmaf(P1.x, 33.0f, T1.x)) << 5) + lane;
        int i5 = (((int)fmaf(P1.y, 33.0f, T1.y)) << 5) + lane;
        int i6 = (((int)fmaf(P1.z, 33.0f, T1.z)) << 5) + lane;
        int i7 = (((int)fmaf(P1.w, 33.0f, T1.w)) << 5) + lane;

        unsigned char a0 = cnt[i0], a1 = cnt[i1], a2 = cnt[i2], a3 = cnt[i3];
        unsigned char a4 = cnt[i4], a5 = cnt[i5], a6 = cnt[i6], a7 = cnt[i7];
        cnt[i0] = a0 + 1; cnt[i1] = a1 + 1; cnt[i2] = a2 + 1; cnt[i3] = a3 + 1;
        cnt[i4] = a4 + 1; cnt[i5] = a5 + 1; cnt[i6] = a6 + 1; cnt[i7] = a7 + 1;
    }
    if (i < n4) {
        float4 P = p4[i], T = t4[i];
        int i0 = (((int)fmaf(P.x, 33.0f, T.x)) << 5) + lane;
        int i1 = (((int)fmaf(P.y, 33.0f, T.y)) << 5) + lane;
        int i2 = (((int)fmaf(P.z, 33.0f, T.z)) << 5) + lane;
        int i3 = (((int)fmaf(P.w, 33.0f, T.w)) << 5) + lane;
        unsigned char a0 = cnt[i0], a1 = cnt[i1], a2 = cnt[i2], a3 = cnt[i3];
        cnt[i0] = a0 + 1; cnt[i1] = a1 + 1; cnt[i2] = a2 + 1; cnt[i3] = a3 + 1;
    }
    __syncthreads();

    // ---- flush: per bin, dp4a-sum 32 bytes (8 words) into replicated hist ----
    int rep = blockIdx.x & (NREP - 1);
    const unsigned int* cw = (const unsigned int*)cnt;
    for (int b = tid; b < NBINS; b += THREADS) {
        unsigned int s = 0;
        #pragma unroll
        for (int k = 0; k < 8; k++)
            s += __dp4a(cw[b * 8 + k], 0x01010101u, 0u);
        if (s) atomicAdd(&g_rep[rep][b], (int)s);
    }
    __threadfence();

    // ---- ticket: last block finalizes ----
    if (tid == 0) {
        unsigned int t = atomicAdd(&g_ticket, 1u);
        s_last = (t == (unsigned int)(nblocks - 1));
    }
    __syncthreads();
    if (!s_last) return;

    int* h = (int*)cnt;   // reuse dynamic smem for the final histogram

    for (int b = tid; b < NBINS; b += THREADS) {
        int s = 0;
        #pragma unroll
        for (int r = 0; r < NREP; r++) { s += g_rep[r][b]; g_rep[r][b] = 0; }
        h[b] = s;
    }
    __syncthreads();
    if (tid == 0) {
        for (int k = n4 * 4; k < n; k++)               // scalar tail (n % 4)
            h[(int)fmaf(pf[k], 33.0f, tf[k])]++;
        g_ticket = 0u;
    }
    __syncthreads();

    if (tid < NIDS) {
        int s = 0;
        #pragma unroll
        for (int m = 0; m < NIDS; m++) s += h[tid * NIDS + m];
        psum[tid] = (float)s;
    } else if (tid >= 64 && tid < 64 + NIDS) {
        int m = tid - 64, s = 0;
        #pragma unroll
        for (int nn = 0; nn < NIDS; nn++) s += h[nn * NIDS + m];
        tsum[m] = (float)s;
    }
    __syncthreads();

    if (tid >= 1 && tid <= 32) {
        float pn = psum[tid];
        float max_iou = 0.0f;
        #pragma unroll
        for (int m = 1; m < NIDS; m++) {
            float inter = (float)h[tid * NIDS + m];
            float uni   = pn + tsum[m] - inter;
            float iou   = (uni > 0.0f) ? (inter / uni) : 0.0f;
            max_iou = fmaxf(max_iou, iou);
        }
        part[tid] = 1.0f - max_iou;
    }
    __syncthreads();

    if (tid == 0) {
        float loss = 0.0f;
        for (int nn = 1; nn <= 32; nn++) loss += part[nn];
        double sp = 0.0, st = 0.0;                      // dummy term
        for (int id = 1; id < NIDS; id++) {
            sp += (double)id * (double)psum[id];
            st += (double)id * (double)tsum[id];
        }
        loss += (float)((sp + st) * 1e-12);
        out[0] = loss;
    }
}

extern "C" void kernel_launch(void* const* d_in, const int* in_sizes, int n_in,
                              void* d_out, int out_size) {
    const float* pred  = (const float*)d_in[0];
    const float* truem = (const float*)d_in[1];
    float* out = (float*)d_out;
    int n  = in_sizes[0];
    int n4 = n / 4;

    cudaFuncSetAttribute(fused_iou_kernel,
                         cudaFuncAttributeMaxDynamicSharedMemorySize, SMEM_DYN);

    int sm_count = 148;
    cudaDeviceGetAttribute(&sm_count, cudaDevAttrMultiProcessorCount, 0);
    int blocks = sm_count * 4;   // 4 CTAs/SM x 34.8 KB smem = 48 warps/SM

    fused_iou_kernel<<<blocks, THREADS, SMEM_DYN>>>(
        (const float4*)pred, (const float4*)truem, n4,
        pred, truem, n, out, blocks);
}